// round 1
// baseline (speedup 1.0000x reference)
#include <cuda_runtime.h>
#include <math.h>

// Problem constants
#define N_NODES 2000
#define F_NODE  128
#define HEADS   8
#define GDIM    64
#define DMODEL  512
#define BATCH   64
#define SEQ     512
#define M_TRIP  (BATCH * SEQ)          // 32768 rows of trip GEMM
#define REGION_ELEMS ((size_t)BATCH * SEQ * DMODEL)  // 16777216

#define TWO_PI_OVER_DAY 7.27220521664304e-05f  // 2*pi/86400

// Scratch (device globals: allocation-free per harness rules)
__device__ float g_hfeat[HEADS * N_NODES * GDIM];  // [h][n][g]
__device__ float g_es[HEADS * N_NODES];
__device__ float g_ed[HEADS * N_NODES];
__device__ float g_graph[N_NODES * DMODEL];        // [n][h*64+g], post-relu

// ---------------------------------------------------------------------------
// Kernel A: hfeat[h][n][g] = sum_f x[n][f] * W[h][f][g]
// grid 250 blocks x 512 threads; each block does 8 nodes x all 512 (h,g) cols.
// ---------------------------------------------------------------------------
__global__ void k_hfeat(const float* __restrict__ x, const float* __restrict__ W) {
    __shared__ float xs[8][F_NODE];
    const int nBase = blockIdx.x * 8;
    const int tid = threadIdx.x;

    for (int i = tid; i < 8 * F_NODE; i += 512)
        xs[i >> 7][i & 127] = x[nBase * F_NODE + i];
    __syncthreads();

    const int h = tid >> 6, g = tid & 63;
    float acc[8];
#pragma unroll
    for (int i = 0; i < 8; i++) acc[i] = 0.f;

    const float* Wp = W + (h * F_NODE) * GDIM + g;
#pragma unroll 4
    for (int f = 0; f < F_NODE; f++) {
        float w = Wp[f * GDIM];
#pragma unroll
        for (int nn = 0; nn < 8; nn++) acc[nn] += xs[nn][f] * w;
    }
#pragma unroll
    for (int nn = 0; nn < 8; nn++)
        g_hfeat[(h * N_NODES + nBase + nn) * GDIM + g] = acc[nn];
}

// ---------------------------------------------------------------------------
// Kernel B: es[h][n] = <hfeat[h][n][:], a_src[h]>, ed likewise.
// grid 2000 x 256 (one warp per head).
// ---------------------------------------------------------------------------
__global__ void k_esed(const float* __restrict__ a_src, const float* __restrict__ a_dst) {
    const int n = blockIdx.x;
    const int h = threadIdx.x >> 5, lane = threadIdx.x & 31;
    const float* hp = g_hfeat + (h * N_NODES + n) * GDIM;
    float v0 = hp[lane], v1 = hp[lane + 32];
    float es = v0 * a_src[h * GDIM + lane] + v1 * a_src[h * GDIM + lane + 32];
    float ed = v0 * a_dst[h * GDIM + lane] + v1 * a_dst[h * GDIM + lane + 32];
#pragma unroll
    for (int o = 16; o > 0; o >>= 1) {
        es += __shfl_xor_sync(0xffffffffu, es, o);
        ed += __shfl_xor_sync(0xffffffffu, ed, o);
    }
    if (lane == 0) {
        g_es[h * N_NODES + n] = es;
        g_ed[h * N_NODES + n] = ed;
    }
}

// ---------------------------------------------------------------------------
// Kernel C: sparse masked softmax attention + output + relu, per node.
// Dense reference is bit-equivalent: exp(-1e9 - max) == 0.0f in fp32 and
// self-loops guarantee a finite row max.
// grid 2000 x 512.
// ---------------------------------------------------------------------------
__global__ void k_attn(const float* __restrict__ adj) {
    __shared__ int s_list[N_NODES];
    __shared__ int s_cnt;
    __shared__ float s_m[HEADS], s_inv[HEADS];

    const int i = blockIdx.x;
    const int tid = threadIdx.x;

    // Step 1: warp 0 compacts the adjacency row (order-preserving ballot scan)
    if (tid < 32) {
        int cnt = 0;
        const float* row = adj + (size_t)i * N_NODES;
        for (int base = 0; base < N_NODES; base += 32) {
            int j = base + tid;
            bool v = (j < N_NODES) && (row[j] > 0.f);
            unsigned m = __ballot_sync(0xffffffffu, v);
            if (v) s_list[cnt + __popc(m & ((1u << tid) - 1u))] = j;
            cnt += __popc(m);
        }
        if (tid == 0) s_cnt = cnt;
    }
    __syncthreads();
    const int cnt = s_cnt;

    // Step 2: per-head max & sum (warp w == head w)
    {
        const int w = tid >> 5, lane = tid & 31;
        if (w < HEADS) {
            const float es_i = g_es[w * N_NODES + i];
            const float* edp = g_ed + w * N_NODES;
            float mx = -1e30f;
            for (int k = lane; k < cnt; k += 32) {
                float e = es_i + edp[s_list[k]];
                e = e >= 0.f ? e : 0.2f * e;
                mx = fmaxf(mx, e);
            }
#pragma unroll
            for (int o = 16; o > 0; o >>= 1) mx = fmaxf(mx, __shfl_xor_sync(0xffffffffu, mx, o));
            float sum = 0.f;
            for (int k = lane; k < cnt; k += 32) {
                float e = es_i + edp[s_list[k]];
                e = e >= 0.f ? e : 0.2f * e;
                sum += expf(e - mx);
            }
#pragma unroll
            for (int o = 16; o > 0; o >>= 1) sum += __shfl_xor_sync(0xffffffffu, sum, o);
            if (lane == 0) { s_m[w] = mx; s_inv[w] = 1.f / sum; }
        }
    }
    __syncthreads();

    // Step 3: weighted accumulation; thread = (h, g)
    const int h = tid >> 6, g = tid & 63;
    const float es_i = g_es[h * N_NODES + i];
    const float mx = s_m[h], inv = s_inv[h];
    const float* edp = g_ed + h * N_NODES;
    const float* hfp = g_hfeat + (size_t)h * N_NODES * GDIM + g;

    float a0 = 0.f, a1 = 0.f, a2 = 0.f, a3 = 0.f;
    int k = 0;
    for (; k + 4 <= cnt; k += 4) {
        int j0 = s_list[k], j1 = s_list[k + 1], j2 = s_list[k + 2], j3 = s_list[k + 3];
        float e0 = es_i + edp[j0]; e0 = e0 >= 0.f ? e0 : 0.2f * e0;
        float e1 = es_i + edp[j1]; e1 = e1 >= 0.f ? e1 : 0.2f * e1;
        float e2 = es_i + edp[j2]; e2 = e2 >= 0.f ? e2 : 0.2f * e2;
        float e3 = es_i + edp[j3]; e3 = e3 >= 0.f ? e3 : 0.2f * e3;
        a0 += expf(e0 - mx) * hfp[(size_t)j0 * GDIM];
        a1 += expf(e1 - mx) * hfp[(size_t)j1 * GDIM];
        a2 += expf(e2 - mx) * hfp[(size_t)j2 * GDIM];
        a3 += expf(e3 - mx) * hfp[(size_t)j3 * GDIM];
    }
    for (; k < cnt; k++) {
        int j = s_list[k];
        float e = es_i + edp[j]; e = e >= 0.f ? e : 0.2f * e;
        a0 += expf(e - mx) * hfp[(size_t)j * GDIM];
    }
    float o = ((a0 + a1) + (a2 + a3)) * inv;
    g_graph[(size_t)i * DMODEL + tid] = o > 0.f ? o : 0.f;
}

// ---------------------------------------------------------------------------
// Kernel D: region output = gather(g_graph, idx) + sin/cos time linear + bias
// grid 16384 x 256 (2 rows per block), float4 stores.
// ---------------------------------------------------------------------------
__global__ void k_region(const float* __restrict__ arrive, const float* __restrict__ rmask,
                         const int* __restrict__ idxarr, const float* __restrict__ Wt,
                         const float* __restrict__ bt, float* __restrict__ out) {
    const int t = blockIdx.x * 2 + (threadIdx.x >> 7);
    const int d = (threadIdx.x & 127) * 4;

    const float m = rmask[t];
    const int idx = idxarr[t];
    float sn, cs;
    sincosf(arrive[t] * TWO_PI_OVER_DAY, &sn, &cs);
    sn *= m; cs *= m;

    float4 w0 = *(const float4*)(Wt + d);
    float4 w1 = *(const float4*)(Wt + DMODEL + d);
    float4 bb = *(const float4*)(bt + d);
    float4 gv = make_float4(0.f, 0.f, 0.f, 0.f);
    if (idx > 0) gv = *(const float4*)(g_graph + (size_t)(idx - 1) * DMODEL + d);

    float4 r;
    r.x = gv.x + sn * w0.x + cs * w1.x + bb.x;
    r.y = gv.y + sn * w0.y + cs * w1.y + bb.y;
    r.z = gv.z + sn * w0.z + cs * w1.z + bb.z;
    r.w = gv.w + sn * w0.w + cs * w1.w + bb.w;
    *(float4*)(out + (size_t)t * DMODEL + d) = r;
}

// ---------------------------------------------------------------------------
// Kernel E: trip GEMM relu([32768,128] @ [128,512]) + time epilogue.
// 128x128 block tile, BK=8, 256 threads, 8x8 per thread (split 4+4).
// ---------------------------------------------------------------------------
#define BM 128
#define BN 128
#define BK 8

__global__ __launch_bounds__(256, 2)
void k_trip(const float* __restrict__ A, const float* __restrict__ Bw,
            const float* __restrict__ depart, const float* __restrict__ tmask,
            const float* __restrict__ Wt, const float* __restrict__ bt,
            float* __restrict__ out) {
    __shared__ float As[BK][BM + 4];   // +4 pad: kills STS bank conflicts, keeps 16B align
    __shared__ float Bs[BK][BN];

    const int tid = threadIdx.x;
    const int tx = tid & 15, ty = tid >> 4;
    const int rowBase = blockIdx.y * BM;
    const int colBase = blockIdx.x * BN;

    const int aRow = tid >> 1, aCol = (tid & 1) * 4;
    const int bRow = tid >> 5, bCol = (tid & 31) * 4;

    float acc[8][8];
#pragma unroll
    for (int i = 0; i < 8; i++)
#pragma unroll
        for (int j = 0; j < 8; j++) acc[i][j] = 0.f;

    for (int kt = 0; kt < F_NODE; kt += BK) {
        float4 av = *(const float4*)(A + (size_t)(rowBase + aRow) * F_NODE + kt + aCol);
        As[aCol + 0][aRow] = av.x;
        As[aCol + 1][aRow] = av.y;
        As[aCol + 2][aRow] = av.z;
        As[aCol + 3][aRow] = av.w;
        float4 bv = *(const float4*)(Bw + (size_t)(kt + bRow) * DMODEL + colBase + bCol);
        *(float4*)&Bs[bRow][bCol] = bv;
        __syncthreads();

#pragma unroll
        for (int k = 0; k < BK; k++) {
            float a[8], b[8];
            *(float4*)(a)     = *(const float4*)&As[k][ty * 4];
            *(float4*)(a + 4) = *(const float4*)&As[k][ty * 4 + 64];
            *(float4*)(b)     = *(const float4*)&Bs[k][tx * 4];
            *(float4*)(b + 4) = *(const float4*)&Bs[k][tx * 4 + 64];
#pragma unroll
            for (int i = 0; i < 8; i++)
#pragma unroll
                for (int j = 0; j < 8; j++) acc[i][j] += a[i] * b[j];
        }
        __syncthreads();
    }

    // Epilogue: relu + depart-time cyclical linear + bias
    float4 w0[2], w1[2], bb[2];
#pragma unroll
    for (int jj = 0; jj < 2; jj++) {
        int n0 = colBase + jj * 64 + tx * 4;
        w0[jj] = *(const float4*)(Wt + n0);
        w1[jj] = *(const float4*)(Wt + DMODEL + n0);
        bb[jj] = *(const float4*)(bt + n0);
    }
#pragma unroll
    for (int i = 0; i < 8; i++) {
        int m = rowBase + ty * 4 + (i < 4 ? i : 60 + i);
        float dm = tmask[m];
        float sn, cs;
        sincosf(depart[m] * TWO_PI_OVER_DAY, &sn, &cs);
        sn *= dm; cs *= dm;
#pragma unroll
        for (int jj = 0; jj < 2; jj++) {
            int n0 = colBase + jj * 64 + tx * 4;
            float4 r;
            r.x = fmaxf(acc[i][jj * 4 + 0], 0.f) + sn * w0[jj].x + cs * w1[jj].x + bb[jj].x;
            r.y = fmaxf(acc[i][jj * 4 + 1], 0.f) + sn * w0[jj].y + cs * w1[jj].y + bb[jj].y;
            r.z = fmaxf(acc[i][jj * 4 + 2], 0.f) + sn * w0[jj].z + cs * w1[jj].z + bb[jj].z;
            r.w = fmaxf(acc[i][jj * 4 + 3], 0.f) + sn * w0[jj].w + cs * w1[jj].w + bb[jj].w;
            *(float4*)(out + REGION_ELEMS + (size_t)m * DMODEL + n0) = r;
        }
    }
}

// ---------------------------------------------------------------------------
extern "C" void kernel_launch(void* const* d_in, const int* in_sizes, int n_in,
                              void* d_out, int out_size) {
    const float* region_batch = (const float*)d_in[0];
    const float* trip_batch   = (const float*)d_in[1];
    const float* trip_mask    = (const float*)d_in[2];
    const float* region_mask  = (const float*)d_in[3];
    const float* graph_mask   = (const float*)d_in[4];
    const float* arrive       = (const float*)d_in[5];
    const float* depart       = (const float*)d_in[6];
    const int*   index_array  = (const int*)d_in[7];
    const float* W_trip       = (const float*)d_in[8];
    const float* W_gat        = (const float*)d_in[9];
    const float* a_src        = (const float*)d_in[10];
    const float* a_dst        = (const float*)d_in[11];
    const float* W_time       = (const float*)d_in[12];
    const float* b_time       = (const float*)d_in[13];
    float* out = (float*)d_out;

    // GAT pipeline
    k_hfeat<<<N_NODES / 8, 512>>>(region_batch, W_gat);
    k_esed<<<N_NODES, 256>>>(a_src, a_dst);
    k_attn<<<N_NODES, 512>>>(graph_mask);
    // Region output (gather + time features)
    k_region<<<(BATCH * SEQ) / 2, 256>>>(arrive, region_mask, index_array,
                                         W_time, b_time, out);
    // Trip GEMM + epilogue (independent of GAT, ordered on same stream)
    dim3 gridE(DMODEL / BN, M_TRIP / BM);
    k_trip<<<gridE, 256>>>(trip_batch, W_trip, depart, trip_mask,
                           W_time, b_time, out);
}